// round 12
// baseline (speedup 1.0000x reference)
#include <cuda_runtime.h>
#include <stdint.h>

// Problem constants (match reference)
#define HOP        160
#define FFT        1024
#define NUM_LABELS 72
#define BATCH      4
#define TLEN       240000
#define PAD        (FFT / 2)           // 512
#define LPAD       (TLEN + 2 * PAD)    // 241024
#define NOUT       ((LPAD - FFT) / HOP + 1)  // 1501

#define W_RUN          4
#define WARPS_PER_CTA  4
#define BLOCK          (WARPS_PER_CTA * 32)
#define RUNS_PER_B     ((NOUT + W_RUN - 1) / W_RUN)                        // 376
#define CTAS_X         ((RUNS_PER_B + WARPS_PER_CTA - 1) / WARPS_PER_CTA)  // 94

// Interior runs touch only unpadded indices in [0, TLEN): run in [1, 373]
#define RUN_INT_LO 1
#define RUN_INT_HI 373

__device__ __forceinline__ int reflect_idx(int j)
{
    int o = j - PAD;
    if (o < 0) o = -o;
    else if (o >= TLEN) o = 2 * (TLEN - 1) - o;
    return o;
}

// Warp-aggregated histogram update: lanes holding equal labels elect one
// leader that issues a single atomic of the group count. Cuts active ATOMS
// lanes from 32 to ~26 (E[distinct of 32 uniform over 72]).
__device__ __forceinline__ void agg_add(int* __restrict__ h, int v, int lane)
{
    unsigned m = __match_any_sync(0xFFFFFFFFu, v);
    if (lane == __ffs(m) - 1) atomicAdd(&h[v], __popc(m));
}
__device__ __forceinline__ void agg_sub(int* __restrict__ h, int v, int lane)
{
    unsigned m = __match_any_sync(0xFFFFFFFFu, v);
    if (lane == __ffs(m) - 1) atomicSub(&h[v], __popc(m));
}

// Warp-wide argmax over 72 bins, lowest-label tie-break (matches jnp.argmax):
// pack count<<7 | (127-label), take max.
__device__ __forceinline__ void scan_and_write(const int* __restrict__ h,
                                               float* __restrict__ orow,
                                               int w, int lane)
{
    int p = (h[lane] << 7) | (127 - lane);
    int q = (h[lane + 32] << 7) | (127 - (lane + 32));
    p = max(p, q);
    if (lane < NUM_LABELS - 64) {
        q = (h[lane + 64] << 7) | (127 - (lane + 64));
        p = max(p, q);
    }
    #pragma unroll
    for (int off = 16; off > 0; off >>= 1)
        p = max(p, __shfl_xor_sync(0xFFFFFFFFu, p, off));
    if (lane == 0) orow[w] = (float)(127 - (p & 127));
}

__global__ void __launch_bounds__(BLOCK)
label_majority_warpslide_agg(const int* __restrict__ lbl, float* __restrict__ out)
{
    __shared__ int hist[WARPS_PER_CTA][NUM_LABELS];

    const int lane = threadIdx.x & 31;
    const int wid  = threadIdx.x >> 5;
    const int b    = blockIdx.y;
    const int run  = blockIdx.x * WARPS_PER_CTA + wid;
    if (run >= RUNS_PER_B) return;

    const int w0 = run * W_RUN;

    const int* __restrict__ row  = lbl + (size_t)b * TLEN;
    float* __restrict__     orow = out + (size_t)b * NOUT;
    int* __restrict__       h    = hist[wid];

    // zero private histogram
    h[lane] = 0;
    h[lane + 32] = 0;
    if (lane < NUM_LABELS - 64) h[lane + 64] = 0;
    __syncwarp();

    if (run >= RUN_INT_LO && run <= RUN_INT_HI) {
        // ================= interior fast path (branch-free, vectorized) ====
        const int* __restrict__ base = row + (w0 * HOP - PAD);  // int4-aligned

        // ---- build window w0: 8 x int4 per lane (high MLP) ----
        int4 v[8];
        #pragma unroll
        for (int k = 0; k < 8; k++)
            v[k] = *(const int4*)(base + k * 128 + lane * 4);
        #pragma unroll
        for (int k = 0; k < 8; k++) {
            agg_add(h, v[k].x, lane);
            agg_add(h, v[k].y, lane);
            agg_add(h, v[k].z, lane);
            agg_add(h, v[k].w, lane);
        }
        __syncwarp();

        // ---- slide: prefetch labels, scan previous window, then update ----
        #pragma unroll
        for (int i = 1; i < W_RUN; i++) {
            const int* __restrict__ ob = base + (i - 1) * HOP;  // leaving
            const int* __restrict__ nb = ob + FFT;              // entering
            int4 o4 = *(const int4*)(ob + lane * 4);
            int  os = ob[128 + lane];
            int4 n4 = *(const int4*)(nb + lane * 4);
            int  ns = nb[128 + lane];

            scan_and_write(h, orow, w0 + i - 1, lane);
            __syncwarp();   // scan reads done before updates

            agg_sub(h, o4.x, lane); agg_sub(h, o4.y, lane);
            agg_sub(h, o4.z, lane); agg_sub(h, o4.w, lane);
            agg_sub(h, os, lane);
            agg_add(h, n4.x, lane); agg_add(h, n4.y, lane);
            agg_add(h, n4.z, lane); agg_add(h, n4.w, lane);
            agg_add(h, ns, lane);
            __syncwarp();   // updates visible before next scan
        }
        scan_and_write(h, orow, w0 + W_RUN - 1, lane);
    } else {
        // ================= edge path (reflect handling, scalar) ============
        const int start = w0 * HOP;
        #pragma unroll
        for (int k = 0; k < FFT / 32; k++) {
            int j = start + lane + k * 32;
            agg_add(h, row[reflect_idx(j)], lane);
        }
        __syncwarp();
        scan_and_write(h, orow, w0, lane);

        #pragma unroll
        for (int i = 1; i < W_RUN; i++) {
            const int w = w0 + i;
            if (w >= NOUT) break;
            __syncwarp();
            const int bidx = (w - 1) * HOP;
            #pragma unroll
            for (int k = 0; k < HOP / 32; k++) {
                int jo = bidx + lane + k * 32;
                int jn = bidx + FFT + lane + k * 32;
                agg_sub(h, row[reflect_idx(jo)], lane);
                agg_add(h, row[reflect_idx(jn)], lane);
            }
            __syncwarp();
            scan_and_write(h, orow, w, lane);
        }
    }
}

extern "C" void kernel_launch(void* const* d_in, const int* in_sizes, int n_in,
                              void* d_out, int out_size)
{
    const int* lbl = (const int*)d_in[0];   // [B, T] int32
    // d_in[1]: all-ones conv weight — irrelevant (window sum == histogram).
    float* out = (float*)d_out;             // [B, NOUT], compared as float32

    dim3 grid(CTAS_X, BATCH);
    label_majority_warpslide_agg<<<grid, BLOCK>>>(lbl, out);
}

// round 13
// speedup vs baseline: 1.9263x; 1.9263x over previous
#include <cuda_runtime.h>
#include <stdint.h>
#include <limits.h>

// Problem constants (match reference)
#define HOP        160
#define FFT        1024
#define NUM_LABELS 72
#define BATCH      4
#define TLEN       240000
#define PAD        (FFT / 2)           // 512
#define LPAD       (TLEN + 2 * PAD)    // 241024
#define NOUT       ((LPAD - FFT) / HOP + 1)  // 1501

#define WARPS      8
#define BLOCK      (WARPS * 32)
#define CTAS_X     ((NOUT + WARPS - 1) / WARPS)   // 188
#define NWORDS     18     // 72 bins, byte-packed 4 per u32
#define PITCH      33     // padded lane pitch -> reduce reads conflict-free

// Interior windows: all unpadded indices in [0, TLEN).
// w>=4: 160*4-512=128>=0. w<=1496: 1496*160-512+1023=239871<240000.
#define W_INT_LO 4
#define W_INT_HI 1496

__device__ __forceinline__ int reflect_idx(int j)   // j = padded index
{
    int o = j - PAD;
    if (o < 0) o = -o;
    else if (o >= TLEN) o = 2 * (TLEN - 1) - o;
    return o;
}

// Non-atomic update of this lane's private column.
__device__ __forceinline__ void upd(uint32_t* __restrict__ h, int lane, int v)
{
    uint32_t idx = (uint32_t)(v >> 2) * PITCH + lane;
    h[idx] += 1u << ((v & 3) * 8);
}

// Argmax over packed u16x2 accumulators (lane r<18 owns bins 4r..4r+3),
// lowest-label tie-break (matches jnp.argmax).
__device__ __forceinline__ void scan_write(uint32_t accE, uint32_t accO,
                                           int lane, float* __restrict__ orow,
                                           int w)
{
    int p = INT_MIN;
    if (lane < NWORDS) {
        int b0 = 4 * lane;
        p =         ((int)(accE & 0xFFFFu) << 7) | (127 - b0);
        p = max(p, ((int)(accO & 0xFFFFu) << 7) | (127 - (b0 + 1)));
        p = max(p, ((int)(accE >> 16)     << 7) | (127 - (b0 + 2)));
        p = max(p, ((int)(accO >> 16)     << 7) | (127 - (b0 + 3)));
    }
    p = __reduce_max_sync(0xFFFFFFFFu, p);
    if (lane == 0) orow[w] = (float)(127 - (p & 127));
}

__global__ void __launch_bounds__(BLOCK)
label_majority_lanehist(const int* __restrict__ lbl, float* __restrict__ out)
{
    // Per-warp: hist[word][lane] with padded pitch. 18*33*4 = 2376 B/warp.
    __shared__ uint32_t hist[WARPS][NWORDS * PITCH];

    const int lane = threadIdx.x & 31;
    const int wid  = threadIdx.x >> 5;
    const int b    = blockIdx.y;
    const int w    = blockIdx.x * WARPS + wid;    // window index
    if (w >= NOUT) return;

    const int* __restrict__ row = lbl + (size_t)b * TLEN;
    uint32_t* __restrict__  h   = hist[wid];

    // zero own column (conflict-free: bank (r+lane)%32 distinct per r)
    #pragma unroll
    for (int r = 0; r < NWORDS; r++)
        h[r * PITCH + lane] = 0;
    // no sync needed: each lane only writes its own column until the reduce

    if (w >= W_INT_LO && w <= W_INT_HI) {
        // interior: vectorized loads, offset is 16B-aligned (160w-512 mod 16 == 0)
        const int* __restrict__ base = row + (w * HOP - PAD);
        int4 v[8];
        #pragma unroll
        for (int k = 0; k < 8; k++)
            v[k] = *(const int4*)(base + k * 128 + lane * 4);
        #pragma unroll
        for (int k = 0; k < 8; k++) {
            upd(h, lane, v[k].x);
            upd(h, lane, v[k].y);
            upd(h, lane, v[k].z);
            upd(h, lane, v[k].w);
        }
    } else {
        // edge: scalar loads through reflect mapping
        const int start = w * HOP;
        #pragma unroll
        for (int k = 0; k < FFT / 32; k++) {
            int j = start + k * 32 + lane;
            upd(h, lane, row[reflect_idx(j)]);
        }
    }
    __syncwarp();   // all columns written before cross-lane reduce

    // reduce: lane r (<18) sums word-row r over the 32 lane-columns.
    // addr = r*33 + k -> bank (r+k)%32: conflict-free across lanes.
    uint32_t accE = 0, accO = 0;
    if (lane < NWORDS) {
        const uint32_t* __restrict__ rw = h + lane * PITCH;
        #pragma unroll
        for (int k = 0; k < 32; k++) {
            uint32_t u = rw[k];
            accE += u & 0x00FF00FFu;           // bins (4r, 4r+2) as u16x2
            accO += (u >> 8) & 0x00FF00FFu;    // bins (4r+1, 4r+3)
        }
    }
    scan_write(accE, accO, lane, out + (size_t)b * NOUT, w);
}

extern "C" void kernel_launch(void* const* d_in, const int* in_sizes, int n_in,
                              void* d_out, int out_size)
{
    const int* lbl = (const int*)d_in[0];   // [B, T] int32
    // d_in[1]: all-ones conv weight — irrelevant (window sum == histogram).
    float* out = (float*)d_out;             // [B, NOUT], compared as float32

    dim3 grid(CTAS_X, BATCH);
    label_majority_lanehist<<<grid, BLOCK>>>(lbl, out);
}

// round 14
// speedup vs baseline: 2.3333x; 1.2113x over previous
#include <cuda_runtime.h>
#include <stdint.h>
#include <limits.h>

// Problem constants (match reference)
#define HOP        160
#define FFT        1024
#define NUM_LABELS 72
#define BATCH      4
#define TLEN       240000
#define PAD        (FFT / 2)           // 512
#define LPAD       (TLEN + 2 * PAD)    // 241024
#define NOUT       ((LPAD - FFT) / HOP + 1)  // 1501

// Window w = padded [160w, 160w+1024) = segments [5w, 5w+32), segment = 32 el.
#define SEGLEN        32
#define SEGS_PER_WIN  32
#define WINS_PER_CTA  32
#define SEGS_PER_CTA  187                 // 5*32 + 27
#define TOTAL_SEGS    (LPAD / SEGLEN)     // 7532
#define NCOLS         18                  // 72 bins byte-packed 4-per-u32
#define WARPS         8
#define BLOCK         (WARPS * 32)
#define CTAS_X        47                  // ceil(1501/32)
#define W_PER_WARP    4

__device__ __forceinline__ int reflect_idx(int j)   // j = padded index
{
    int o = j - PAD;
    if (o < 0) o = -o;
    else if (o >= TLEN) o = 2 * (TLEN - 1) - o;
    return o;
}

// Argmax over packed u16x2 accumulators (lane c<18 owns bins 4c..4c+3),
// lowest-label tie-break (matches jnp.argmax).
__device__ __forceinline__ void scan_write(uint32_t accE, uint32_t accO,
                                           int lane, float* __restrict__ orow,
                                           int w)
{
    int p = INT_MIN;
    if (lane < NCOLS) {
        int b0 = 4 * lane;
        p =         ((int)(accE & 0xFFFFu) << 7) | (127 - b0);
        p = max(p, ((int)(accO & 0xFFFFu) << 7) | (127 - (b0 + 1)));
        p = max(p, ((int)(accE >> 16)     << 7) | (127 - (b0 + 2)));
        p = max(p, ((int)(accO >> 16)     << 7) | (127 - (b0 + 3)));
    }
    p = __reduce_max_sync(0xFFFFFFFFu, p);
    if (lane == 0 && w < NOUT)
        orow[w] = (float)(127 - (p & 127));
}

__global__ void __launch_bounds__(BLOCK)
label_majority_seghist3(const int* __restrict__ lbl, float* __restrict__ out)
{
    // Column-major packed segment histograms sh[col*187 + seg].
    __shared__ uint32_t sh[NCOLS * SEGS_PER_CTA];

    const int tid  = threadIdx.x;
    const int lane = tid & 31;
    const int wid  = tid >> 5;
    const int b    = blockIdx.y;
    const int bx   = blockIdx.x;
    const int w0   = bx * WINS_PER_CTA;
    const int gseg0 = 5 * w0;             // = 160*bx

    const int* __restrict__ row  = lbl + (size_t)b * TLEN;
    float* __restrict__     orow = out + (size_t)b * NOUT;

    for (int i = tid; i < NCOLS * SEGS_PER_CTA; i += BLOCK)
        sh[i] = 0;
    __syncthreads();

    // ============ phase 1: one segment per lane, collision-free ATOMS ======
    // Warps 0..5 each own 32 segments (lane = segment). All 32 lanes of an
    // atomic step hit DISTINCT words ((v>>2)*187 + seg, seg distinct) ->
    // zero same-word replays. Loads: 8 int4 per lane, issued up-front (MLP=8).
    if (wid < 6) {
        const int seg  = wid * 32 + lane;
        const int gseg = gseg0 + seg;
        if (seg < SEGS_PER_CTA && gseg < TOTAL_SEGS) {
            int v[32];
            if (bx >= 1 && bx <= 45) {
                // interior: unpadded, 16B-aligned (128*gseg - 2048 bytes)
                const int4* __restrict__ p =
                    (const int4*)(row + (gseg * SEGLEN - PAD));
                int4 q[8];
                #pragma unroll
                for (int k = 0; k < 8; k++) q[k] = p[k];
                #pragma unroll
                for (int k = 0; k < 8; k++) {
                    v[4*k]   = q[k].x; v[4*k+1] = q[k].y;
                    v[4*k+2] = q[k].z; v[4*k+3] = q[k].w;
                }
            } else {
                // edge: reflect-mapped scalar loads, all issued before atomics
                const int j0 = gseg * SEGLEN;
                #pragma unroll
                for (int k = 0; k < SEGLEN; k++)
                    v[k] = row[reflect_idx(j0 + k)];
            }
            #pragma unroll
            for (int k = 0; k < SEGLEN; k++)
                atomicAdd(&sh[(v[k] >> 2) * SEGS_PER_CTA + seg],
                          1u << ((v[k] & 3) * 8));
        }
    }
    __syncthreads();

    // ============ phase 2: sliding window sums (no atomics; verified) ======
    // Warp handles windows w0 + 4*wid + i. Lane c<18 owns bins 4c..4c+3,
    // u8x4 -> u16x2 accumulation (window sums <= 1024 fit u16).
    // Pitch 187 odd -> per-lane column reads bank-conflict-free.
    const int wrel0 = wid * W_PER_WARP;
    const uint32_t* __restrict__ col = sh + lane * SEGS_PER_CTA;
    const int srel0 = 5 * wrel0;

    uint32_t accE = 0, accO = 0;
    if (lane < NCOLS) {
        #pragma unroll
        for (int k = 0; k < SEGS_PER_WIN; k++) {
            uint32_t u = col[srel0 + k];
            accE += u & 0x00FF00FFu;
            accO += (u >> 8) & 0x00FF00FFu;
        }
    }
    scan_write(accE, accO, lane, orow, w0 + wrel0);

    #pragma unroll
    for (int i = 1; i < W_PER_WARP; i++) {
        if (lane < NCOLS) {
            const int so = srel0 + 5 * (i - 1);
            #pragma unroll
            for (int k = 0; k < 5; k++) {
                uint32_t uo = col[so + k];                  // leaving segs
                uint32_t un = col[so + SEGS_PER_WIN + k];   // entering segs
                accE += (un & 0x00FF00FFu)        - (uo & 0x00FF00FFu);
                accO += ((un >> 8) & 0x00FF00FFu) - ((uo >> 8) & 0x00FF00FFu);
            }
        }
        scan_write(accE, accO, lane, orow, w0 + wrel0 + i);
    }
}

extern "C" void kernel_launch(void* const* d_in, const int* in_sizes, int n_in,
                              void* d_out, int out_size)
{
    const int* lbl = (const int*)d_in[0];   // [B, T] int32
    // d_in[1]: all-ones conv weight — irrelevant (window sum == histogram).
    float* out = (float*)d_out;             // [B, NOUT], compared as float32

    dim3 grid(CTAS_X, BATCH);
    label_majority_seghist3<<<grid, BLOCK>>>(lbl, out);
}